// round 2
// baseline (speedup 1.0000x reference)
#include <cuda_runtime.h>
#include <cuda_bf16.h>

// Problem constants (fixed by the dataset)
#define BATCH    2
#define SEQ      2048
#define DMODEL   1024
#define NHEADS   16
#define HEADDIM  64
#define MTOT     (BATCH * SEQ)       // 4096 rows for the projections

// ---------------------------------------------------------------------------
// Scratch: __device__ globals (allocation-free, graph-capture safe)
// Q/K/V stored [B, H, S, Hd]; AO stored [B, S, D]
// ---------------------------------------------------------------------------
__device__ float g_Q [BATCH * NHEADS * SEQ * HEADDIM];
__device__ float g_K [BATCH * NHEADS * SEQ * HEADDIM];
__device__ float g_V [BATCH * NHEADS * SEQ * HEADDIM];
__device__ float g_AO[BATCH * SEQ * DMODEL];

// ---------------------------------------------------------------------------
// SGEMM: C[M,N] = A[M,K] @ B[K,N] + bias[N]
// 128x128 block tile, K-chunk 8, 256 threads, 8x8 microtile per thread.
// mode 0: scatter output into [B, H, S, Hd] (for Q/K/V)
// mode 1: plain row-major [M, N]            (for attention-out @ Wo)
// ---------------------------------------------------------------------------
#define GM 128
#define GN 128
#define GK 8

__global__ __launch_bounds__(256, 2)
void sgemm_kernel(const float* __restrict__ A, const float* __restrict__ B,
                  const float* __restrict__ bias, float* __restrict__ C,
                  int M, int N, int K, int mode)
{
    __shared__ __align__(16) float As[GK][GM];   // transposed A tile
    __shared__ __align__(16) float Bs[GK][GN];

    const int tid = threadIdx.x;
    const int bm = blockIdx.y;
    const int bn = blockIdx.x;

    const float* Ab = A + (size_t)bm * GM * K;
    const float* Bb = B + (size_t)bn * GN;

    // load mapping
    const int arow = tid >> 1;            // 0..127
    const int acol = (tid & 1) * 4;       // 0 or 4
    const int brow = tid >> 5;            // 0..7
    const int bcol = (tid & 31) * 4;      // 0..124

    // compute mapping
    const int trow = (tid >> 4) * 8;      // 0..120
    const int tcol = (tid & 15) * 8;      // 0..120

    float acc[8][8];
#pragma unroll
    for (int i = 0; i < 8; i++)
#pragma unroll
        for (int j = 0; j < 8; j++) acc[i][j] = 0.0f;

    for (int kt = 0; kt < K; kt += GK) {
        float4 a4 = *(const float4*)(Ab + (size_t)arow * K + kt + acol);
        As[acol + 0][arow] = a4.x;
        As[acol + 1][arow] = a4.y;
        As[acol + 2][arow] = a4.z;
        As[acol + 3][arow] = a4.w;
        float4 b4 = *(const float4*)(Bb + (size_t)(kt + brow) * N + bcol);
        *(float4*)&Bs[brow][bcol] = b4;
        __syncthreads();

#pragma unroll
        for (int k = 0; k < GK; k++) {
            float ra[8], rb[8];
            *(float4*)(ra + 0) = *(const float4*)&As[k][trow + 0];
            *(float4*)(ra + 4) = *(const float4*)&As[k][trow + 4];
            *(float4*)(rb + 0) = *(const float4*)&Bs[k][tcol + 0];
            *(float4*)(rb + 4) = *(const float4*)&Bs[k][tcol + 4];
#pragma unroll
            for (int i = 0; i < 8; i++)
#pragma unroll
                for (int j = 0; j < 8; j++)
                    acc[i][j] += ra[i] * rb[j];
        }
        __syncthreads();
    }

    // epilogue
#pragma unroll
    for (int i = 0; i < 8; i++) {
        const int m = bm * GM + trow + i;
#pragma unroll
        for (int j = 0; j < 8; j++) {
            const int n = bn * GN + tcol + j;
            float v = acc[i][j] + bias[n];
            if (mode == 0) {
                // m = b*SEQ + s ; n = h*HEADDIM + d  ->  [B,H,S,Hd]
                const int b = m >> 11;          // /2048
                const int s = m & 2047;
                const int h = n >> 6;           // /64
                const int d = n & 63;
                C[(((size_t)(b * NHEADS + h) * SEQ + s) << 6) + d] = v;
            } else {
                C[(size_t)m * N + n] = v;
            }
        }
    }
}

// ---------------------------------------------------------------------------
// Flash-style ALiBi attention.
// Grid: (SEQ/64, NHEADS, BATCH), 256 threads.
// Per CTA: 64 q-rows; loop over 64-wide K/V chunks; online softmax.
// Thread grid 16x16: ty -> 4 q-rows, tx -> 4 k-cols (phase 1) / 4 d-cols (phase 2).
// ---------------------------------------------------------------------------
#define BQ   64
#define BKC  64
#define PAD  65   // smem row stride (odd -> at worst 2-way conflicts on K reads)

__global__ __launch_bounds__(256, 2)
void attn_kernel(const float* __restrict__ Q, const float* __restrict__ K,
                 const float* __restrict__ V, float* __restrict__ AO)
{
    extern __shared__ float sm[];
    float* Qs = sm;                    // [64][PAD]
    float* Ks = Qs + BQ * PAD;
    float* Vs = Ks + BKC * PAD;
    float* Ps = Vs + BKC * PAD;

    const int tid = threadIdx.x;
    const int qt = blockIdx.x;
    const int h  = blockIdx.y;
    const int b  = blockIdx.z;

    const float* Qb = Q + (((size_t)(b * NHEADS + h) * SEQ + qt * BQ) << 6);
    const float* Kb = K + (((size_t)(b * NHEADS + h) * SEQ) << 6);
    const float* Vb = V + (((size_t)(b * NHEADS + h) * SEQ) << 6);

    // ---- load Q tile (64x64) ----
#pragma unroll
    for (int t = 0; t < 4; t++) {
        int idx = tid + t * 256;                // float4 index, 0..1023
        int row = idx >> 4;
        int c4  = (idx & 15) * 4;
        float4 v4 = *(const float4*)(Qb + row * HEADDIM + c4);
        Qs[row * PAD + c4 + 0] = v4.x;
        Qs[row * PAD + c4 + 1] = v4.y;
        Qs[row * PAD + c4 + 2] = v4.z;
        Qs[row * PAD + c4 + 3] = v4.w;
    }

    const int ty = tid >> 4;
    const int tx = tid & 15;
    const int q0 = qt * BQ + ty * 4;            // first global q-row of this thread

    float o[4][4];
    float mrow[4], lrow[4];
#pragma unroll
    for (int i = 0; i < 4; i++) {
        mrow[i] = -1e30f;
        lrow[i] = 0.0f;
#pragma unroll
        for (int j = 0; j < 4; j++) o[i][j] = 0.0f;
    }

    const float slope = exp2f(-(float)h / (float)NHEADS);
    const float scale = 0.125f;                 // HEADDIM^-0.5

    for (int kt = 0; kt < SEQ; kt += BKC) {
        // ---- load K and V chunks ----
#pragma unroll
        for (int t = 0; t < 4; t++) {
            int idx = tid + t * 256;
            int row = idx >> 4;
            int c4  = (idx & 15) * 4;
            float4 kv = *(const float4*)(Kb + (size_t)(kt + row) * HEADDIM + c4);
            Ks[row * PAD + c4 + 0] = kv.x;
            Ks[row * PAD + c4 + 1] = kv.y;
            Ks[row * PAD + c4 + 2] = kv.z;
            Ks[row * PAD + c4 + 3] = kv.w;
            float4 vv = *(const float4*)(Vb + (size_t)(kt + row) * HEADDIM + c4);
            Vs[row * PAD + c4 + 0] = vv.x;
            Vs[row * PAD + c4 + 1] = vv.y;
            Vs[row * PAD + c4 + 2] = vv.z;
            Vs[row * PAD + c4 + 3] = vv.w;
        }
        __syncthreads();

        // ---- S = Q K^T (64x64x64) ----
        float s[4][4];
#pragma unroll
        for (int i = 0; i < 4; i++)
#pragma unroll
            for (int j = 0; j < 4; j++) s[i][j] = 0.0f;

#pragma unroll 8
        for (int d = 0; d < HEADDIM; d++) {
            float rq[4], rk[4];
#pragma unroll
            for (int i = 0; i < 4; i++) rq[i] = Qs[(ty * 4 + i) * PAD + d];
#pragma unroll
            for (int j = 0; j < 4; j++) rk[j] = Ks[(tx * 4 + j) * PAD + d];
#pragma unroll
            for (int i = 0; i < 4; i++)
#pragma unroll
                for (int j = 0; j < 4; j++)
                    s[i][j] += rq[i] * rk[j];
        }

        // ---- ALiBi + online softmax update (per q-row, half-warp reductions) ----
#pragma unroll
        for (int i = 0; i < 4; i++) {
            const float qg = (float)(q0 + i);
            float sv[4];
            float rowmax = -1e30f;
#pragma unroll
            for (int j = 0; j < 4; j++) {
                const float kg = (float)(kt + tx * 4 + j);
                sv[j] = s[i][j] * scale + slope * (kg - qg);
                rowmax = fmaxf(rowmax, sv[j]);
            }
#pragma unroll
            for (int mask = 1; mask < 16; mask <<= 1)
                rowmax = fmaxf(rowmax, __shfl_xor_sync(0xffffffffu, rowmax, mask));

            const float mnew = fmaxf(mrow[i], rowmax);
            const float corr = __expf(mrow[i] - mnew);
            float psum = 0.0f;
#pragma unroll
            for (int j = 0; j < 4; j++) {
                const float p = __expf(sv[j] - mnew);
                Ps[(ty * 4 + i) * PAD + tx * 4 + j] = p;
                psum += p;
            }
#pragma unroll
            for (int mask = 1; mask < 16; mask <<= 1)
                psum += __shfl_xor_sync(0xffffffffu, psum, mask);

            lrow[i] = lrow[i] * corr + psum;
            mrow[i] = mnew;
#pragma unroll
            for (int j = 0; j < 4; j++) o[i][j] *= corr;
        }
        __syncthreads();

        // ---- O += P V (64x64x64) ----
#pragma unroll 8
        for (int kk = 0; kk < BKC; kk++) {
            float rp[4], rv[4];
#pragma unroll
            for (int i = 0; i < 4; i++) rp[i] = Ps[(ty * 4 + i) * PAD + kk];
#pragma unroll
            for (int j = 0; j < 4; j++) rv[j] = Vs[kk * PAD + tx * 4 + j];
#pragma unroll
            for (int i = 0; i < 4; i++)
#pragma unroll
                for (int j = 0; j < 4; j++)
                    o[i][j] += rp[i] * rv[j];
        }
        __syncthreads();
    }

    // ---- normalize and write AO[b, q, h*64 + d] ----
#pragma unroll
    for (int i = 0; i < 4; i++) {
        const float inv = 1.0f / lrow[i];
        const int qg = q0 + i;
        float* dst = AO + ((size_t)(b * SEQ + qg) * DMODEL) + h * HEADDIM + tx * 4;
#pragma unroll
        for (int j = 0; j < 4; j++) dst[j] = o[i][j] * inv;
    }
}

// ---------------------------------------------------------------------------
// Launcher
// ---------------------------------------------------------------------------
extern "C" void kernel_launch(void* const* d_in, const int* in_sizes, int n_in,
                              void* d_out, int out_size)
{
    const float* x  = (const float*)d_in[0];
    const float* Wq = (const float*)d_in[1];
    const float* bq = (const float*)d_in[2];
    const float* Wk = (const float*)d_in[3];
    const float* bk = (const float*)d_in[4];
    const float* Wv = (const float*)d_in[5];
    const float* bv = (const float*)d_in[6];
    const float* Wo = (const float*)d_in[7];
    const float* bo = (const float*)d_in[8];
    float* out = (float*)d_out;

    float *gQ, *gK, *gV, *gAO;
    cudaGetSymbolAddress((void**)&gQ,  g_Q);
    cudaGetSymbolAddress((void**)&gK,  g_K);
    cudaGetSymbolAddress((void**)&gV,  g_V);
    cudaGetSymbolAddress((void**)&gAO, g_AO);

    const int smem_attn = 4 * BKC * PAD * (int)sizeof(float);   // 66,560 B
    cudaFuncSetAttribute(attn_kernel, cudaFuncAttributeMaxDynamicSharedMemorySize, smem_attn);

    dim3 ggrid(DMODEL / GN, MTOT / GM);   // (8, 32)
    dim3 gblk(256);

    // Q/K/V projections (scatter into [B,H,S,Hd])
    sgemm_kernel<<<ggrid, gblk>>>(x, Wq, bq, gQ, MTOT, DMODEL, DMODEL, 0);
    sgemm_kernel<<<ggrid, gblk>>>(x, Wk, bk, gK, MTOT, DMODEL, DMODEL, 0);
    sgemm_kernel<<<ggrid, gblk>>>(x, Wv, bv, gV, MTOT, DMODEL, DMODEL, 0);

    // Attention
    dim3 agrid(SEQ / BQ, NHEADS, BATCH);  // (32, 16, 2)
    attn_kernel<<<agrid, gblk, smem_attn>>>(gQ, gK, gV, gAO);

    // Output projection
    sgemm_kernel<<<ggrid, gblk>>>(gAO, Wo, bo, out, MTOT, DMODEL, DMODEL, 1);
}

// round 5
// speedup vs baseline: 1.2932x; 1.2932x over previous
#include <cuda_runtime.h>
#include <cuda_bf16.h>
#include <cstdint>

// Problem constants (fixed by the dataset)
#define BATCH    2
#define SEQ      2048
#define DMODEL   1024
#define NHEADS   16
#define HEADDIM  64
#define MTOT     (BATCH * SEQ)       // 4096 rows for the projections

// ---------------------------------------------------------------------------
// Scratch: __device__ globals (allocation-free, graph-capture safe)
// ---------------------------------------------------------------------------
__device__ float g_Q [BATCH * NHEADS * SEQ * HEADDIM];
__device__ float g_K [BATCH * NHEADS * SEQ * HEADDIM];
__device__ float g_V [BATCH * NHEADS * SEQ * HEADDIM];
__device__ float g_AO[BATCH * SEQ * DMODEL];
__device__ float g_Wt[4 * DMODEL * DMODEL];     // transposed weights [N][K] x4

// ---------------------------------------------------------------------------
// tf32 helpers (sm_80+ baseline PTX — valid on sm_100 plain target)
// ---------------------------------------------------------------------------
__device__ __forceinline__ uint32_t f32_to_tf32(float f) {
    uint32_t u;
    asm("cvt.rna.tf32.f32 %0, %1;" : "=r"(u) : "f"(f));
    return u;
}

// D = A(16x8) @ B(8x8) + C, tf32 inputs, fp32 accumulate.
__device__ __forceinline__ void mma_tf32_16x8x8(float c[4], const uint32_t a[4],
                                                const uint32_t b[2]) {
    asm volatile(
        "mma.sync.aligned.m16n8k8.row.col.f32.tf32.tf32.f32 "
        "{%0,%1,%2,%3}, {%4,%5,%6,%7}, {%8,%9}, {%0,%1,%2,%3};"
        : "+f"(c[0]), "+f"(c[1]), "+f"(c[2]), "+f"(c[3])
        : "r"(a[0]), "r"(a[1]), "r"(a[2]), "r"(a[3]), "r"(b[0]), "r"(b[1]));
}

// ---------------------------------------------------------------------------
// Transpose: Wt[n][k] = W[k][n] for the 4 weight matrices (one launch)
// ---------------------------------------------------------------------------
__global__ void transpose4_kernel(const float* __restrict__ W0, const float* __restrict__ W1,
                                  const float* __restrict__ W2, const float* __restrict__ W3)
{
    __shared__ float t[32][33];
    const float* src = (blockIdx.z == 0) ? W0 : (blockIdx.z == 1) ? W1
                     : (blockIdx.z == 2) ? W2 : W3;
    float* dst = g_Wt + (size_t)blockIdx.z * DMODEL * DMODEL;

    int x = blockIdx.x * 32 + threadIdx.x;
    int y = blockIdx.y * 32 + threadIdx.y;
#pragma unroll
    for (int j = 0; j < 32; j += 8)
        t[threadIdx.y + j][threadIdx.x] = src[(size_t)(y + j) * DMODEL + x];
    __syncthreads();
    int x2 = blockIdx.y * 32 + threadIdx.x;
    int y2 = blockIdx.x * 32 + threadIdx.y;
#pragma unroll
    for (int j = 0; j < 32; j += 8)
        dst[(size_t)(y2 + j) * DMODEL + x2] = t[threadIdx.x][threadIdx.y + j];
}

// ---------------------------------------------------------------------------
// tf32 mma.sync GEMM: C[M,N] = A[M,1024] @ Bt[N,1024]^T + bias
// CTA: 128x128 tile, 256 threads = 8 warps (4 M x 2 N), warp tile 32x64.
// K-chunk 32 (4 k-steps of 8). Operands converted to tf32 at smem store.
// mode 0: scatter to [B,H,S,Hd]; mode 1: row-major [M,1024].
// ---------------------------------------------------------------------------
#define KC   32
#define KPAD 36   // smem row stride in words

__global__ __launch_bounds__(256, 1)
void gemm_mma_kernel(const float* __restrict__ A, const float* __restrict__ Bt,
                     const float* __restrict__ bias, float* __restrict__ C, int mode)
{
    __shared__ uint32_t As[128 * KPAD];   // [m][k] tf32
    __shared__ uint32_t Bs[128 * KPAD];   // [n][k] tf32

    const int tid = threadIdx.x;
    const int wid = tid >> 5;
    const int lane = tid & 31;
    const int gid = lane >> 2;            // 0..7
    const int ctid = lane & 3;            // 0..3

    const int warp_m = (wid & 3) * 32;    // 0,32,64,96
    const int warp_n = (wid >> 2) * 64;   // 0,64

    const int n0 = blockIdx.x * 128;
    const int m0 = blockIdx.y * 128;

    // load mapping: 1024 float4 per tile, 4 per thread per tile
    const int lrow = tid >> 1;                 // 0..127 (two threads per row)
    const int lc4a = (tid & 1) * 16;           // 0 or 16 (float col base, 4 float4 each)

    float acc[2][8][4];
#pragma unroll
    for (int i = 0; i < 2; i++)
#pragma unroll
        for (int j = 0; j < 8; j++)
#pragma unroll
            for (int r = 0; r < 4; r++) acc[i][j][r] = 0.0f;

    for (int kc = 0; kc < DMODEL; kc += KC) {
        // ---- load + convert tiles ----
        const float* Ab = A  + (size_t)(m0 + lrow) * DMODEL + kc + lc4a;
        const float* Bb = Bt + (size_t)(n0 + lrow) * DMODEL + kc + lc4a;
#pragma unroll
        for (int t = 0; t < 4; t++) {
            float4 av = *(const float4*)(Ab + t * 4);
            uint32_t* da = &As[lrow * KPAD + lc4a + t * 4];
            da[0] = f32_to_tf32(av.x); da[1] = f32_to_tf32(av.y);
            da[2] = f32_to_tf32(av.z); da[3] = f32_to_tf32(av.w);
            float4 bv = *(const float4*)(Bb + t * 4);
            uint32_t* db = &Bs[lrow * KPAD + lc4a + t * 4];
            db[0] = f32_to_tf32(bv.x); db[1] = f32_to_tf32(bv.y);
            db[2] = f32_to_tf32(bv.z); db[3] = f32_to_tf32(bv.w);
        }
        __syncthreads();

        // ---- 4 k-steps of 8 ----
#pragma unroll
        for (int ks = 0; ks < 4; ks++) {
            const int kb = ks * 8;
            uint32_t afr[2][4];
#pragma unroll
            for (int i = 0; i < 2; i++) {
                const int r = warp_m + i * 16 + gid;
                afr[i][0] = As[(r)     * KPAD + kb + ctid];
                afr[i][1] = As[(r + 8) * KPAD + kb + ctid];
                afr[i][2] = As[(r)     * KPAD + kb + ctid + 4];
                afr[i][3] = As[(r + 8) * KPAD + kb + ctid + 4];
            }
            uint32_t bfr[8][2];
#pragma unroll
            for (int j = 0; j < 8; j++) {
                const int cn = warp_n + j * 8 + gid;
                bfr[j][0] = Bs[cn * KPAD + kb + ctid];
                bfr[j][1] = Bs[cn * KPAD + kb + ctid + 4];
            }
#pragma unroll
            for (int i = 0; i < 2; i++)
#pragma unroll
                for (int j = 0; j < 8; j++)
                    mma_tf32_16x8x8(acc[i][j], afr[i], bfr[j]);
        }
        __syncthreads();
    }

    // ---- epilogue: write C + bias ----
#pragma unroll
    for (int i = 0; i < 2; i++) {
#pragma unroll
        for (int half = 0; half < 2; half++) {         // c0/c1 vs c2/c3 rows
            const int m = m0 + warp_m + i * 16 + gid + half * 8;
            const int b = m >> 11, s = m & 2047;
#pragma unroll
            for (int j = 0; j < 8; j++) {
                const int n = n0 + warp_n + j * 8 + ctid * 2;
                const float v0 = acc[i][j][half * 2 + 0] + bias[n];
                const float v1 = acc[i][j][half * 2 + 1] + bias[n + 1];
                float* dst;
                if (mode == 0) {
                    const int h = n >> 6, d0 = n & 63;
                    dst = C + ((((size_t)(b * NHEADS + h) * SEQ + s) << 6) + d0);
                } else {
                    dst = C + (size_t)m * DMODEL + n;
                }
                dst[0] = v0;
                dst[1] = v1;
            }
        }
    }
}

// ---------------------------------------------------------------------------
// Flash-style ALiBi attention (unchanged from passing round-2 kernel).
// ---------------------------------------------------------------------------
#define BQ   64
#define BKC  64
#define PAD  65

__global__ __launch_bounds__(256, 2)
void attn_kernel(const float* __restrict__ Q, const float* __restrict__ K,
                 const float* __restrict__ V, float* __restrict__ AO)
{
    extern __shared__ float sm[];
    float* Qs = sm;
    float* Ks = Qs + BQ * PAD;
    float* Vs = Ks + BKC * PAD;
    float* Ps = Vs + BKC * PAD;

    const int tid = threadIdx.x;
    const int qt = blockIdx.x;
    const int h  = blockIdx.y;
    const int b  = blockIdx.z;

    const float* Qb = Q + (((size_t)(b * NHEADS + h) * SEQ + qt * BQ) << 6);
    const float* Kb = K + (((size_t)(b * NHEADS + h) * SEQ) << 6);
    const float* Vb = V + (((size_t)(b * NHEADS + h) * SEQ) << 6);

#pragma unroll
    for (int t = 0; t < 4; t++) {
        int idx = tid + t * 256;
        int row = idx >> 4;
        int c4  = (idx & 15) * 4;
        float4 v4 = *(const float4*)(Qb + row * HEADDIM + c4);
        Qs[row * PAD + c4 + 0] = v4.x;
        Qs[row * PAD + c4 + 1] = v4.y;
        Qs[row * PAD + c4 + 2] = v4.z;
        Qs[row * PAD + c4 + 3] = v4.w;
    }

    const int ty = tid >> 4;
    const int tx = tid & 15;
    const int q0 = qt * BQ + ty * 4;

    float o[4][4];
    float mrow[4], lrow[4];
#pragma unroll
    for (int i = 0; i < 4; i++) {
        mrow[i] = -1e30f;
        lrow[i] = 0.0f;
#pragma unroll
        for (int j = 0; j < 4; j++) o[i][j] = 0.0f;
    }

    const float slope = exp2f(-(float)h / (float)NHEADS);
    const float scale = 0.125f;

    for (int kt = 0; kt < SEQ; kt += BKC) {
#pragma unroll
        for (int t = 0; t < 4; t++) {
            int idx = tid + t * 256;
            int row = idx >> 4;
            int c4  = (idx & 15) * 4;
            float4 kv = *(const float4*)(Kb + (size_t)(kt + row) * HEADDIM + c4);
            Ks[row * PAD + c4 + 0] = kv.x;
            Ks[row * PAD + c4 + 1] = kv.y;
            Ks[row * PAD + c4 + 2] = kv.z;
            Ks[row * PAD + c4 + 3] = kv.w;
            float4 vv = *(const float4*)(Vb + (size_t)(kt + row) * HEADDIM + c4);
            Vs[row * PAD + c4 + 0] = vv.x;
            Vs[row * PAD + c4 + 1] = vv.y;
            Vs[row * PAD + c4 + 2] = vv.z;
            Vs[row * PAD + c4 + 3] = vv.w;
        }
        __syncthreads();

        float s[4][4];
#pragma unroll
        for (int i = 0; i < 4; i++)
#pragma unroll
            for (int j = 0; j < 4; j++) s[i][j] = 0.0f;

#pragma unroll 8
        for (int d = 0; d < HEADDIM; d++) {
            float rq[4], rk[4];
#pragma unroll
            for (int i = 0; i < 4; i++) rq[i] = Qs[(ty * 4 + i) * PAD + d];
#pragma unroll
            for (int j = 0; j < 4; j++) rk[j] = Ks[(tx * 4 + j) * PAD + d];
#pragma unroll
            for (int i = 0; i < 4; i++)
#pragma unroll
                for (int j = 0; j < 4; j++)
                    s[i][j] += rq[i] * rk[j];
        }

#pragma unroll
        for (int i = 0; i < 4; i++) {
            const float qg = (float)(q0 + i);
            float sv[4];
            float rowmax = -1e30f;
#pragma unroll
            for (int j = 0; j < 4; j++) {
                const float kg = (float)(kt + tx * 4 + j);
                sv[j] = s[i][j] * scale + slope * (kg - qg);
                rowmax = fmaxf(rowmax, sv[j]);
            }
#pragma unroll
            for (int mask = 1; mask < 16; mask <<= 1)
                rowmax = fmaxf(rowmax, __shfl_xor_sync(0xffffffffu, rowmax, mask));

            const float mnew = fmaxf(mrow[i], rowmax);
            const float corr = __expf(mrow[i] - mnew);
            float psum = 0.0f;
#pragma unroll
            for (int j = 0; j < 4; j++) {
                const float p = __expf(sv[j] - mnew);
                Ps[(ty * 4 + i) * PAD + tx * 4 + j] = p;
                psum += p;
            }
#pragma unroll
            for (int mask = 1; mask < 16; mask <<= 1)
                psum += __shfl_xor_sync(0xffffffffu, psum, mask);

            lrow[i] = lrow[i] * corr + psum;
            mrow[i] = mnew;
#pragma unroll
            for (int j = 0; j < 4; j++) o[i][j] *= corr;
        }
        __syncthreads();

#pragma unroll 8
        for (int kk = 0; kk < BKC; kk++) {
            float rp[4], rv[4];
#pragma unroll
            for (int i = 0; i < 4; i++) rp[i] = Ps[(ty * 4 + i) * PAD + kk];
#pragma unroll
            for (int j = 0; j < 4; j++) rv[j] = Vs[kk * PAD + tx * 4 + j];
#pragma unroll
            for (int i = 0; i < 4; i++)
#pragma unroll
                for (int j = 0; j < 4; j++)
                    o[i][j] += rp[i] * rv[j];
        }
        __syncthreads();
    }

#pragma unroll
    for (int i = 0; i < 4; i++) {
        const float inv = 1.0f / lrow[i];
        const int qg = q0 + i;
        float* dst = AO + ((size_t)(b * SEQ + qg) * DMODEL) + h * HEADDIM + tx * 4;
#pragma unroll
        for (int j = 0; j < 4; j++) dst[j] = o[i][j] * inv;
    }
}

// ---------------------------------------------------------------------------
// Launcher
// ---------------------------------------------------------------------------
extern "C" void kernel_launch(void* const* d_in, const int* in_sizes, int n_in,
                              void* d_out, int out_size)
{
    const float* x  = (const float*)d_in[0];
    const float* Wq = (const float*)d_in[1];
    const float* bq = (const float*)d_in[2];
    const float* Wk = (const float*)d_in[3];
    const float* bk = (const float*)d_in[4];
    const float* Wv = (const float*)d_in[5];
    const float* bv = (const float*)d_in[6];
    const float* Wo = (const float*)d_in[7];
    const float* bo = (const float*)d_in[8];
    float* out = (float*)d_out;

    float *gQ, *gK, *gV, *gAO, *gWt;
    cudaGetSymbolAddress((void**)&gQ,  g_Q);
    cudaGetSymbolAddress((void**)&gK,  g_K);
    cudaGetSymbolAddress((void**)&gV,  g_V);
    cudaGetSymbolAddress((void**)&gAO, g_AO);
    cudaGetSymbolAddress((void**)&gWt, g_Wt);

    const int smem_attn = 4 * BKC * PAD * (int)sizeof(float);   // 66,560 B
    cudaFuncSetAttribute(attn_kernel, cudaFuncAttributeMaxDynamicSharedMemorySize, smem_attn);

    // One-time weight transposes (all 4 in one launch)
    transpose4_kernel<<<dim3(DMODEL / 32, DMODEL / 32, 4), dim3(32, 8)>>>(Wq, Wk, Wv, Wo);

    dim3 ggrid(DMODEL / 128, MTOT / 128);   // (8, 32)

    // Q/K/V projections on tensor cores (scatter into [B,H,S,Hd])
    gemm_mma_kernel<<<ggrid, 256>>>(x, gWt + 0 * DMODEL * DMODEL, bq, gQ, 0);
    gemm_mma_kernel<<<ggrid, 256>>>(x, gWt + 1 * DMODEL * DMODEL, bk, gK, 0);
    gemm_mma_kernel<<<ggrid, 256>>>(x, gWt + 2 * DMODEL * DMODEL, bv, gV, 0);

    // Attention (unchanged SIMT fp32)
    dim3 agrid(SEQ / BQ, NHEADS, BATCH);  // (32, 16, 2)
    attn_kernel<<<agrid, 256, smem_attn>>>(gQ, gK, gV, gAO);

    // Output projection on tensor cores
    gemm_mma_kernel<<<ggrid, 256>>>(gAO, gWt + 3 * DMODEL * DMODEL, bo, out, 1);
}

// round 6
// speedup vs baseline: 2.1302x; 1.6472x over previous
#include <cuda_runtime.h>
#include <cuda_bf16.h>
#include <cstdint>

// Problem constants (fixed by the dataset)
#define BATCH    2
#define SEQ      2048
#define DMODEL   1024
#define NHEADS   16
#define HEADDIM  64
#define MTOT     (BATCH * SEQ)       // 4096 rows for the projections

// ---------------------------------------------------------------------------
// Scratch: __device__ globals (allocation-free, graph-capture safe)
// ---------------------------------------------------------------------------
__device__ float g_Q [BATCH * NHEADS * SEQ * HEADDIM];
__device__ float g_K [BATCH * NHEADS * SEQ * HEADDIM];
__device__ float g_V [BATCH * NHEADS * SEQ * HEADDIM];
__device__ float g_AO[BATCH * SEQ * DMODEL];
__device__ float g_Wt[4 * DMODEL * DMODEL];     // transposed weights [N][K] x4

// ---------------------------------------------------------------------------
// tf32 helpers (sm_80+ baseline PTX — valid on sm_100 plain target)
// ---------------------------------------------------------------------------
__device__ __forceinline__ uint32_t f32_to_tf32(float f) {
    uint32_t u;
    asm("cvt.rna.tf32.f32 %0, %1;" : "=r"(u) : "f"(f));
    return u;
}

// D = A(16x8) @ B(8x8) + C, tf32 inputs, fp32 accumulate.
__device__ __forceinline__ void mma_tf32_16x8x8(float c[4], const uint32_t a[4],
                                                const uint32_t b[2]) {
    asm volatile(
        "mma.sync.aligned.m16n8k8.row.col.f32.tf32.tf32.f32 "
        "{%0,%1,%2,%3}, {%4,%5,%6,%7}, {%8,%9}, {%0,%1,%2,%3};"
        : "+f"(c[0]), "+f"(c[1]), "+f"(c[2]), "+f"(c[3])
        : "r"(a[0]), "r"(a[1]), "r"(a[2]), "r"(a[3]), "r"(b[0]), "r"(b[1]));
}

// ---------------------------------------------------------------------------
// Transpose: Wt[n][k] = W[k][n] for the 4 weight matrices (one launch)
// ---------------------------------------------------------------------------
__global__ void transpose4_kernel(const float* __restrict__ W0, const float* __restrict__ W1,
                                  const float* __restrict__ W2, const float* __restrict__ W3)
{
    __shared__ float t[32][33];
    const float* src = (blockIdx.z == 0) ? W0 : (blockIdx.z == 1) ? W1
                     : (blockIdx.z == 2) ? W2 : W3;
    float* dst = g_Wt + (size_t)blockIdx.z * DMODEL * DMODEL;

    int x = blockIdx.x * 32 + threadIdx.x;
    int y = blockIdx.y * 32 + threadIdx.y;
#pragma unroll
    for (int j = 0; j < 32; j += 8)
        t[threadIdx.y + j][threadIdx.x] = src[(size_t)(y + j) * DMODEL + x];
    __syncthreads();
    int x2 = blockIdx.y * 32 + threadIdx.x;
    int y2 = blockIdx.x * 32 + threadIdx.y;
#pragma unroll
    for (int j = 0; j < 32; j += 8)
        dst[(size_t)(y2 + j) * DMODEL + x2] = t[threadIdx.x][threadIdx.y + j];
}

// ---------------------------------------------------------------------------
// tf32 mma.sync GEMM (unchanged from round-5 passing kernel)
// ---------------------------------------------------------------------------
#define KC   32
#define KPAD 36   // smem row stride in words

__global__ __launch_bounds__(256, 1)
void gemm_mma_kernel(const float* __restrict__ A, const float* __restrict__ Bt,
                     const float* __restrict__ bias, float* __restrict__ C, int mode)
{
    __shared__ uint32_t As[128 * KPAD];   // [m][k] tf32
    __shared__ uint32_t Bs[128 * KPAD];   // [n][k] tf32

    const int tid = threadIdx.x;
    const int wid = tid >> 5;
    const int lane = tid & 31;
    const int gid = lane >> 2;            // 0..7
    const int ctid = lane & 3;            // 0..3

    const int warp_m = (wid & 3) * 32;    // 0,32,64,96
    const int warp_n = (wid >> 2) * 64;   // 0,64

    const int n0 = blockIdx.x * 128;
    const int m0 = blockIdx.y * 128;

    const int lrow = tid >> 1;                 // 0..127 (two threads per row)
    const int lc4a = (tid & 1) * 16;           // 0 or 16

    float acc[2][8][4];
#pragma unroll
    for (int i = 0; i < 2; i++)
#pragma unroll
        for (int j = 0; j < 8; j++)
#pragma unroll
            for (int r = 0; r < 4; r++) acc[i][j][r] = 0.0f;

    for (int kc = 0; kc < DMODEL; kc += KC) {
        const float* Ab = A  + (size_t)(m0 + lrow) * DMODEL + kc + lc4a;
        const float* Bb = Bt + (size_t)(n0 + lrow) * DMODEL + kc + lc4a;
#pragma unroll
        for (int t = 0; t < 4; t++) {
            float4 av = *(const float4*)(Ab + t * 4);
            uint32_t* da = &As[lrow * KPAD + lc4a + t * 4];
            da[0] = f32_to_tf32(av.x); da[1] = f32_to_tf32(av.y);
            da[2] = f32_to_tf32(av.z); da[3] = f32_to_tf32(av.w);
            float4 bv = *(const float4*)(Bb + t * 4);
            uint32_t* db = &Bs[lrow * KPAD + lc4a + t * 4];
            db[0] = f32_to_tf32(bv.x); db[1] = f32_to_tf32(bv.y);
            db[2] = f32_to_tf32(bv.z); db[3] = f32_to_tf32(bv.w);
        }
        __syncthreads();

#pragma unroll
        for (int ks = 0; ks < 4; ks++) {
            const int kb = ks * 8;
            uint32_t afr[2][4];
#pragma unroll
            for (int i = 0; i < 2; i++) {
                const int r = warp_m + i * 16 + gid;
                afr[i][0] = As[(r)     * KPAD + kb + ctid];
                afr[i][1] = As[(r + 8) * KPAD + kb + ctid];
                afr[i][2] = As[(r)     * KPAD + kb + ctid + 4];
                afr[i][3] = As[(r + 8) * KPAD + kb + ctid + 4];
            }
            uint32_t bfr[8][2];
#pragma unroll
            for (int j = 0; j < 8; j++) {
                const int cn = warp_n + j * 8 + gid;
                bfr[j][0] = Bs[cn * KPAD + kb + ctid];
                bfr[j][1] = Bs[cn * KPAD + kb + ctid + 4];
            }
#pragma unroll
            for (int i = 0; i < 2; i++)
#pragma unroll
                for (int j = 0; j < 8; j++)
                    mma_tf32_16x8x8(acc[i][j], afr[i], bfr[j]);
        }
        __syncthreads();
    }

#pragma unroll
    for (int i = 0; i < 2; i++) {
#pragma unroll
        for (int half = 0; half < 2; half++) {
            const int m = m0 + warp_m + i * 16 + gid + half * 8;
            const int b = m >> 11, s = m & 2047;
#pragma unroll
            for (int j = 0; j < 8; j++) {
                const int n = n0 + warp_n + j * 8 + ctid * 2;
                const float v0 = acc[i][j][half * 2 + 0] + bias[n];
                const float v1 = acc[i][j][half * 2 + 1] + bias[n + 1];
                float* dst;
                if (mode == 0) {
                    const int h = n >> 6, d0 = n & 63;
                    dst = C + ((((size_t)(b * NHEADS + h) * SEQ + s) << 6) + d0);
                } else {
                    dst = C + (size_t)m * DMODEL + n;
                }
                dst[0] = v0;
                dst[1] = v1;
            }
        }
    }
}

// ---------------------------------------------------------------------------
// Tensor-core flash attention with ALiBi (mma.sync tf32).
// Grid: (SEQ/128, NHEADS, BATCH), 256 threads = 8 warps; warp w owns q-rows
// [w*16, w*16+16). 64-key chunks; online softmax in C-fragment registers.
// Smem rows padded to 72 words (72 % 32 == 8 -> conflict-free frag gathers).
// ---------------------------------------------------------------------------
#define AQ    128         // q-rows per CTA
#define AK    64          // keys per chunk
#define APW   72          // padded row width (u32 words)

#define AQS_OFF 0
#define AKS_OFF (AQ * APW)                  //  9216
#define AVS_OFF (AKS_OFF + AK * APW)        // 13824
#define APS_OFF (AVS_OFF + AK * APW)        // 18432
#define ATTN_SMEM_WORDS (APS_OFF + AQ * APW)
#define ATTN_SMEM_BYTES (ATTN_SMEM_WORDS * 4)   // 110,592 B

__global__ __launch_bounds__(256, 1)
void attn_mma_kernel(const float* __restrict__ Q, const float* __restrict__ K,
                     const float* __restrict__ V, float* __restrict__ AO)
{
    extern __shared__ uint32_t smw[];
    uint32_t* Qs = smw + AQS_OFF;
    uint32_t* Ks = smw + AKS_OFF;
    uint32_t* Vs = smw + AVS_OFF;
    uint32_t* Ps = smw + APS_OFF;

    const int tid  = threadIdx.x;
    const int wid  = tid >> 5;
    const int lane = tid & 31;
    const int gid  = lane >> 2;     // 0..7
    const int ctid = lane & 3;      // 0..3
    const int wrow = wid * 16;      // warp's first q-row in tile

    const int qt = blockIdx.x;
    const int h  = blockIdx.y;
    const int b  = blockIdx.z;
    const int q0 = qt * AQ;

    const float* Qb = Q + (((size_t)(b * NHEADS + h) * SEQ + q0) << 6);
    const float* Kb = K + (((size_t)(b * NHEADS + h) * SEQ) << 6);
    const float* Vb = V + (((size_t)(b * NHEADS + h) * SEQ) << 6);

    // ---- load Q tile (128x64) as tf32 ----
#pragma unroll
    for (int t = 0; t < 8; t++) {
        int idx = tid + t * 256;                 // float4 idx, 0..2047
        int row = idx >> 4;
        int c4  = (idx & 15) * 4;
        float4 v4 = *(const float4*)(Qb + row * HEADDIM + c4);
        uint32_t* d = &Qs[row * APW + c4];
        d[0] = f32_to_tf32(v4.x); d[1] = f32_to_tf32(v4.y);
        d[2] = f32_to_tf32(v4.z); d[3] = f32_to_tf32(v4.w);
    }

    const float slope = exp2f(-(float)h / (float)NHEADS);
    const float scale = 0.125f;                  // HEADDIM^-0.5
    const float qg0 = (float)(q0 + wrow + gid);
    const float qg1 = qg0 + 8.0f;

    float oacc[8][4];
#pragma unroll
    for (int j = 0; j < 8; j++)
#pragma unroll
        for (int r = 0; r < 4; r++) oacc[j][r] = 0.0f;
    float m0 = -1e30f, m1 = -1e30f, l0 = 0.0f, l1 = 0.0f;

    for (int kt = 0; kt < SEQ; kt += AK) {
        __syncthreads();    // prev PV done reading Vs / first-iter Q store visible
        // ---- load K,V chunk (64x64 each) as tf32 ----
#pragma unroll
        for (int t = 0; t < 4; t++) {
            int idx = tid + t * 256;             // 0..1023
            int row = idx >> 4;
            int c4  = (idx & 15) * 4;
            float4 kv = *(const float4*)(Kb + (size_t)(kt + row) * HEADDIM + c4);
            uint32_t* dk = &Ks[row * APW + c4];
            dk[0] = f32_to_tf32(kv.x); dk[1] = f32_to_tf32(kv.y);
            dk[2] = f32_to_tf32(kv.z); dk[3] = f32_to_tf32(kv.w);
            float4 vv = *(const float4*)(Vb + (size_t)(kt + row) * HEADDIM + c4);
            uint32_t* dv = &Vs[row * APW + c4];
            dv[0] = f32_to_tf32(vv.x); dv[1] = f32_to_tf32(vv.y);
            dv[2] = f32_to_tf32(vv.z); dv[3] = f32_to_tf32(vv.w);
        }
        __syncthreads();

        // ---- S = Q K^T : per warp 16x64, 8 n-tiles x 8 k-steps ----
        float sacc[8][4];
#pragma unroll
        for (int j = 0; j < 8; j++)
#pragma unroll
            for (int r = 0; r < 4; r++) sacc[j][r] = 0.0f;

#pragma unroll
        for (int ks = 0; ks < 8; ks++) {
            const int kb = ks * 8;
            uint32_t a[4];
            a[0] = Qs[(wrow + gid)     * APW + kb + ctid];
            a[1] = Qs[(wrow + gid + 8) * APW + kb + ctid];
            a[2] = Qs[(wrow + gid)     * APW + kb + ctid + 4];
            a[3] = Qs[(wrow + gid + 8) * APW + kb + ctid + 4];
#pragma unroll
            for (int nt = 0; nt < 8; nt++) {
                uint32_t bf[2];
                bf[0] = Ks[(nt * 8 + gid) * APW + kb + ctid];
                bf[1] = Ks[(nt * 8 + gid) * APW + kb + ctid + 4];
                mma_tf32_16x8x8(sacc[nt], a, bf);
            }
        }

        // ---- ALiBi + scale + row max (rows spread over thread quad) ----
        float mx0 = -1e30f, mx1 = -1e30f;
#pragma unroll
        for (int nt = 0; nt < 8; nt++) {
            const float kg = (float)(kt + nt * 8 + 2 * ctid);
            sacc[nt][0] = sacc[nt][0] * scale + slope * (kg        - qg0);
            sacc[nt][1] = sacc[nt][1] * scale + slope * (kg + 1.0f - qg0);
            sacc[nt][2] = sacc[nt][2] * scale + slope * (kg        - qg1);
            sacc[nt][3] = sacc[nt][3] * scale + slope * (kg + 1.0f - qg1);
            mx0 = fmaxf(mx0, fmaxf(sacc[nt][0], sacc[nt][1]));
            mx1 = fmaxf(mx1, fmaxf(sacc[nt][2], sacc[nt][3]));
        }
#pragma unroll
        for (int msk = 1; msk < 4; msk <<= 1) {
            mx0 = fmaxf(mx0, __shfl_xor_sync(0xffffffffu, mx0, msk));
            mx1 = fmaxf(mx1, __shfl_xor_sync(0xffffffffu, mx1, msk));
        }

        const float m0n = fmaxf(m0, mx0);
        const float m1n = fmaxf(m1, mx1);
        const float corr0 = __expf(m0 - m0n);
        const float corr1 = __expf(m1 - m1n);
        m0 = m0n; m1 = m1n;

        // ---- P = exp(S - m), store tf32 to warp-private Ps rows ----
        float ps0 = 0.0f, ps1 = 0.0f;
        const int r0 = wrow + gid, r1 = wrow + gid + 8;
#pragma unroll
        for (int nt = 0; nt < 8; nt++) {
            const int col = nt * 8 + 2 * ctid;
            float p0 = __expf(sacc[nt][0] - m0);
            float p1 = __expf(sacc[nt][1] - m0);
            float p2 = __expf(sacc[nt][2] - m1);
            float p3 = __expf(sacc[nt][3] - m1);
            ps0 += p0 + p1;
            ps1 += p2 + p3;
            uint2 w0 = make_uint2(f32_to_tf32(p0), f32_to_tf32(p1));
            uint2 w1 = make_uint2(f32_to_tf32(p2), f32_to_tf32(p3));
            *(uint2*)&Ps[r0 * APW + col] = w0;
            *(uint2*)&Ps[r1 * APW + col] = w1;
        }
#pragma unroll
        for (int msk = 1; msk < 4; msk <<= 1) {
            ps0 += __shfl_xor_sync(0xffffffffu, ps0, msk);
            ps1 += __shfl_xor_sync(0xffffffffu, ps1, msk);
        }
        l0 = l0 * corr0 + ps0;
        l1 = l1 * corr1 + ps1;

        // rescale O accumulators
#pragma unroll
        for (int nt = 0; nt < 8; nt++) {
            oacc[nt][0] *= corr0; oacc[nt][1] *= corr0;
            oacc[nt][2] *= corr1; oacc[nt][3] *= corr1;
        }
        __syncwarp();   // warp-private Ps rows: no CTA barrier needed

        // ---- O += P V : A = Ps (k = key), B = Vs gathered as col-major ----
#pragma unroll
        for (int ks = 0; ks < 8; ks++) {
            const int kb = ks * 8;
            uint32_t a[4];
            a[0] = Ps[(wrow + gid)     * APW + kb + ctid];
            a[1] = Ps[(wrow + gid + 8) * APW + kb + ctid];
            a[2] = Ps[(wrow + gid)     * APW + kb + ctid + 4];
            a[3] = Ps[(wrow + gid + 8) * APW + kb + ctid + 4];
#pragma unroll
            for (int nt = 0; nt < 8; nt++) {
                uint32_t bf[2];
                bf[0] = Vs[(kb + ctid)     * APW + nt * 8 + gid];
                bf[1] = Vs[(kb + ctid + 4) * APW + nt * 8 + gid];
                mma_tf32_16x8x8(oacc[nt], a, bf);
            }
        }
    }

    // ---- normalize and write AO[b, q, h*64 + d] ----
    const float inv0 = 1.0f / l0;
    const float inv1 = 1.0f / l1;
    const int qr0 = q0 + wrow + gid;
    const int qr1 = qr0 + 8;
    float* dst0 = AO + ((size_t)(b * SEQ + qr0) * DMODEL) + h * HEADDIM;
    float* dst1 = AO + ((size_t)(b * SEQ + qr1) * DMODEL) + h * HEADDIM;
#pragma unroll
    for (int nt = 0; nt < 8; nt++) {
        const int col = nt * 8 + 2 * ctid;
        *(float2*)(dst0 + col) = make_float2(oacc[nt][0] * inv0, oacc[nt][1] * inv0);
        *(float2*)(dst1 + col) = make_float2(oacc[nt][2] * inv1, oacc[nt][3] * inv1);
    }
}

// ---------------------------------------------------------------------------
// Launcher
// ---------------------------------------------------------------------------
extern "C" void kernel_launch(void* const* d_in, const int* in_sizes, int n_in,
                              void* d_out, int out_size)
{
    const float* x  = (const float*)d_in[0];
    const float* Wq = (const float*)d_in[1];
    const float* bq = (const float*)d_in[2];
    const float* Wk = (const float*)d_in[3];
    const float* bk = (const float*)d_in[4];
    const float* Wv = (const float*)d_in[5];
    const float* bv = (const float*)d_in[6];
    const float* Wo = (const float*)d_in[7];
    const float* bo = (const float*)d_in[8];
    float* out = (float*)d_out;

    float *gQ, *gK, *gV, *gAO, *gWt;
    cudaGetSymbolAddress((void**)&gQ,  g_Q);
    cudaGetSymbolAddress((void**)&gK,  g_K);
    cudaGetSymbolAddress((void**)&gV,  g_V);
    cudaGetSymbolAddress((void**)&gAO, g_AO);
    cudaGetSymbolAddress((void**)&gWt, g_Wt);

    cudaFuncSetAttribute(attn_mma_kernel, cudaFuncAttributeMaxDynamicSharedMemorySize,
                         ATTN_SMEM_BYTES);

    // One-time weight transposes (all 4 in one launch)
    transpose4_kernel<<<dim3(DMODEL / 32, DMODEL / 32, 4), dim3(32, 8)>>>(Wq, Wk, Wv, Wo);

    dim3 ggrid(DMODEL / 128, MTOT / 128);   // (8, 32)

    // Q/K/V projections on tensor cores (scatter into [B,H,S,Hd])
    gemm_mma_kernel<<<ggrid, 256>>>(x, gWt + 0 * DMODEL * DMODEL, bq, gQ, 0);
    gemm_mma_kernel<<<ggrid, 256>>>(x, gWt + 1 * DMODEL * DMODEL, bk, gK, 0);
    gemm_mma_kernel<<<ggrid, 256>>>(x, gWt + 2 * DMODEL * DMODEL, bv, gV, 0);

    // Attention on tensor cores
    dim3 agrid(SEQ / AQ, NHEADS, BATCH);    // (16, 16, 2)
    attn_mma_kernel<<<agrid, 256, ATTN_SMEM_BYTES>>>(gQ, gK, gV, gAO);

    // Output projection on tensor cores
    gemm_mma_kernel<<<ggrid, 256>>>(gAO, gWt + 3 * DMODEL * DMODEL, bo, out, 1);
}

// round 9
// speedup vs baseline: 2.6750x; 1.2558x over previous
#include <cuda_runtime.h>
#include <cuda_bf16.h>
#include <cstdint>

// Problem constants (fixed by the dataset)
#define BATCH    2
#define SEQ      2048
#define DMODEL   1024
#define NHEADS   16
#define HEADDIM  64
#define MTOT     (BATCH * SEQ)

// ---------------------------------------------------------------------------
// Scratch (__device__ globals; Q/K/V/AO/Wt/Xt hold tf32-converted bits)
// ---------------------------------------------------------------------------
__device__ uint32_t g_Q [BATCH * NHEADS * SEQ * HEADDIM];
__device__ uint32_t g_K [BATCH * NHEADS * SEQ * HEADDIM];
__device__ uint32_t g_V [BATCH * NHEADS * SEQ * HEADDIM];
__device__ uint32_t g_AO[BATCH * SEQ * DMODEL];
__device__ uint32_t g_Wt[4 * DMODEL * DMODEL];   // transposed weights [N][K], tf32
__device__ uint32_t g_Xt[MTOT * DMODEL];         // x converted to tf32

// ---------------------------------------------------------------------------
// Helpers
// ---------------------------------------------------------------------------
__device__ __forceinline__ uint32_t f32_to_tf32(float f) {
    uint32_t u;
    asm("cvt.rna.tf32.f32 %0, %1;" : "=r"(u) : "f"(f));
    return u;
}

__device__ __forceinline__ void mma_tf32_16x8x8(float c[4], const uint32_t a[4],
                                                const uint32_t b[2]) {
    asm volatile(
        "mma.sync.aligned.m16n8k8.row.col.f32.tf32.tf32.f32 "
        "{%0,%1,%2,%3}, {%4,%5,%6,%7}, {%8,%9}, {%0,%1,%2,%3};"
        : "+f"(c[0]), "+f"(c[1]), "+f"(c[2]), "+f"(c[3])
        : "r"(a[0]), "r"(a[1]), "r"(a[2]), "r"(a[3]), "r"(b[0]), "r"(b[1]));
}

__device__ __forceinline__ uint32_t smem_u32(const void* p) {
    uint32_t a;
    asm("{ .reg .u64 t; cvta.to.shared.u64 t, %1; cvt.u32.u64 %0, t; }" : "=r"(a) : "l"(p));
    return a;
}
__device__ __forceinline__ void cp_async16(uint32_t saddr, const void* gptr) {
    asm volatile("cp.async.ca.shared.global [%0], [%1], 16;" :: "r"(saddr), "l"(gptr));
}
__device__ __forceinline__ void cp_commit() {
    asm volatile("cp.async.commit_group;" ::: "memory");
}
template <int N> __device__ __forceinline__ void cp_wait() {
    asm volatile("cp.async.wait_group %0;" :: "n"(N) : "memory");
}

// ---------------------------------------------------------------------------
// x -> tf32 convert (one pass)
// ---------------------------------------------------------------------------
__global__ void convert_x_kernel(const float* __restrict__ x)
{
    int idx = blockIdx.x * blockDim.x + threadIdx.x;     // float4 index
    float4 v = *(const float4*)(x + idx * 4);
    uint4 o;
    o.x = f32_to_tf32(v.x); o.y = f32_to_tf32(v.y);
    o.z = f32_to_tf32(v.z); o.w = f32_to_tf32(v.w);
    *(uint4*)(g_Xt + idx * 4) = o;
}

// ---------------------------------------------------------------------------
// Transpose + tf32 convert: Wt[n][k] = tf32(W[k][n]) for 4 weights
// ---------------------------------------------------------------------------
__global__ void transpose4_kernel(const float* __restrict__ W0, const float* __restrict__ W1,
                                  const float* __restrict__ W2, const float* __restrict__ W3)
{
    __shared__ float t[32][33];
    const float* src = (blockIdx.z == 0) ? W0 : (blockIdx.z == 1) ? W1
                     : (blockIdx.z == 2) ? W2 : W3;
    uint32_t* dst = g_Wt + (size_t)blockIdx.z * DMODEL * DMODEL;

    int x = blockIdx.x * 32 + threadIdx.x;
    int y = blockIdx.y * 32 + threadIdx.y;
#pragma unroll
    for (int j = 0; j < 32; j += 8)
        t[threadIdx.y + j][threadIdx.x] = src[(size_t)(y + j) * DMODEL + x];
    __syncthreads();
    int x2 = blockIdx.y * 32 + threadIdx.x;
    int y2 = blockIdx.x * 32 + threadIdx.y;
#pragma unroll
    for (int j = 0; j < 32; j += 8)
        dst[(size_t)(y2 + j) * DMODEL + x2] = f32_to_tf32(t[threadIdx.x][threadIdx.y + j]);
}

// ---------------------------------------------------------------------------
// GEMM mainloop shared pieces (2-stage cp.async pipeline)
// CTA 128x128, 256 threads = 8 warps (4M x 2N), warp tile 32x64, KC=32.
// ---------------------------------------------------------------------------
#define KC    32
#define KPAD  36     // 36 % 32 == 4 -> conflict-free fragment gathers
#define TILEW (128 * KPAD)                 // words per tile
#define GEMM_SMEM_BYTES (4 * TILEW * 4)    // 2 stages x (A+B) = 73,728 B

#define GEMM_PROLOG \
    extern __shared__ uint32_t smw[]; \
    const uint32_t sbase = smem_u32(smw); \
    const int tid = threadIdx.x; \
    const int wid = tid >> 5, lane = tid & 31; \
    const int gid = lane >> 2, ctid = lane & 3; \
    const int warp_m = (wid & 3) * 32, warp_n = (wid >> 2) * 64; \
    const int n0 = blockIdx.x * 128, m0 = blockIdx.y * 128; \
    const int lrow = tid >> 1, lc4a = (tid & 1) * 16;

// prefetch stage st, k-chunk kc
#define GEMM_PREFETCH(st, kc) do { \
    const uint32_t* Ab_ = A  + (size_t)(m0 + lrow) * DMODEL + (kc) + lc4a; \
    const uint32_t* Bb_ = Bt + (size_t)(n0 + lrow) * DMODEL + (kc) + lc4a; \
    uint32_t sa_ = sbase + ((st) * TILEW + lrow * KPAD + lc4a) * 4; \
    uint32_t sb_ = sbase + ((2 + (st)) * TILEW + lrow * KPAD + lc4a) * 4; \
    _Pragma("unroll") \
    for (int t_ = 0; t_ < 4; t_++) { \
        cp_async16(sa_ + t_ * 16, Ab_ + t_ * 4); \
        cp_async16(sb_ + t_ * 16, Bb_ + t_ * 4); \
    } \
    cp_commit(); \
} while (0)

#define GEMM_COMPUTE(st) do { \
    const uint32_t* Asw = smw + (st) * TILEW; \
    const uint32_t* Bsw = smw + (2 + (st)) * TILEW; \
    _Pragma("unroll") \
    for (int ks = 0; ks < 4; ks++) { \
        const int kb = ks * 8; \
        uint32_t afr[2][4]; \
        _Pragma("unroll") \
        for (int i = 0; i < 2; i++) { \
            const int r = warp_m + i * 16 + gid; \
            afr[i][0] = Asw[(r)     * KPAD + kb + ctid]; \
            afr[i][1] = Asw[(r + 8) * KPAD + kb + ctid]; \
            afr[i][2] = Asw[(r)     * KPAD + kb + ctid + 4]; \
            afr[i][3] = Asw[(r + 8) * KPAD + kb + ctid + 4]; \
        } \
        uint32_t bfr[8][2]; \
        _Pragma("unroll") \
        for (int j = 0; j < 8; j++) { \
            const int cn = warp_n + j * 8 + gid; \
            bfr[j][0] = Bsw[cn * KPAD + kb + ctid]; \
            bfr[j][1] = Bsw[cn * KPAD + kb + ctid + 4]; \
        } \
        _Pragma("unroll") \
        for (int i = 0; i < 2; i++) \
            _Pragma("unroll") \
            for (int j = 0; j < 8; j++) \
                mma_tf32_16x8x8(acc[i][j], afr[i], bfr[j]); \
    } \
} while (0)

#define GEMM_MAINLOOP do { \
    GEMM_PREFETCH(0, 0); \
    for (int kc = 0; kc < 32; kc++) { \
        const int cur = kc & 1; \
        if (kc + 1 < 32) { GEMM_PREFETCH(cur ^ 1, (kc + 1) * KC); cp_wait<1>(); } \
        else             { cp_wait<0>(); } \
        __syncthreads(); \
        GEMM_COMPUTE(cur); \
        __syncthreads(); \
    } \
} while (0)

// ---- QKV projection: grid (8, 32, 3); writes tf32 into [B,H,S,Hd] ----
__global__ __launch_bounds__(256, 1)
void gemm_qkv_kernel(const uint32_t* __restrict__ A, const uint32_t* __restrict__ WtBase,
                     const float* __restrict__ bq, const float* __restrict__ bk,
                     const float* __restrict__ bv,
                     uint32_t* __restrict__ Qo, uint32_t* __restrict__ Ko,
                     uint32_t* __restrict__ Vo)
{
    GEMM_PROLOG
    const int z = blockIdx.z;
    const uint32_t* Bt = WtBase + (size_t)z * DMODEL * DMODEL;
    const float* bias = (z == 0) ? bq : (z == 1) ? bk : bv;
    uint32_t* C = (z == 0) ? Qo : (z == 1) ? Ko : Vo;

    float acc[2][8][4];
#pragma unroll
    for (int i = 0; i < 2; i++)
#pragma unroll
        for (int j = 0; j < 8; j++)
#pragma unroll
            for (int r = 0; r < 4; r++) acc[i][j][r] = 0.0f;

    GEMM_MAINLOOP;

#pragma unroll
    for (int i = 0; i < 2; i++) {
#pragma unroll
        for (int half = 0; half < 2; half++) {
            const int m = m0 + warp_m + i * 16 + gid + half * 8;
            const int b = m >> 11, s = m & 2047;
#pragma unroll
            for (int j = 0; j < 8; j++) {
                const int n = n0 + warp_n + j * 8 + ctid * 2;
                const int h = n >> 6, d0 = n & 63;
                uint32_t* dst = C + ((((size_t)(b * NHEADS + h) * SEQ + s) << 6) + d0);
                dst[0] = f32_to_tf32(acc[i][j][half * 2 + 0] + bias[n]);
                dst[1] = f32_to_tf32(acc[i][j][half * 2 + 1] + bias[n + 1]);
            }
        }
    }
}

// ---- Output projection: row-major fp32 out ----
__global__ __launch_bounds__(256, 1)
void gemm_out_kernel(const uint32_t* __restrict__ A, const uint32_t* __restrict__ Bt,
                     const float* __restrict__ bias, float* __restrict__ C)
{
    GEMM_PROLOG

    float acc[2][8][4];
#pragma unroll
    for (int i = 0; i < 2; i++)
#pragma unroll
        for (int j = 0; j < 8; j++)
#pragma unroll
            for (int r = 0; r < 4; r++) acc[i][j][r] = 0.0f;

    GEMM_MAINLOOP;

#pragma unroll
    for (int i = 0; i < 2; i++) {
#pragma unroll
        for (int half = 0; half < 2; half++) {
            const int m = m0 + warp_m + i * 16 + gid + half * 8;
#pragma unroll
            for (int j = 0; j < 8; j++) {
                const int n = n0 + warp_n + j * 8 + ctid * 2;
                float* dst = C + (size_t)m * DMODEL + n;
                dst[0] = acc[i][j][half * 2 + 0] + bias[n];
                dst[1] = acc[i][j][half * 2 + 1] + bias[n + 1];
            }
        }
    }
}

// ---------------------------------------------------------------------------
// Tensor-core flash attention with ALiBi (mma.sync tf32), pre-tf32 inputs.
// Grid (16,16,2), 256 threads = 8 warps, warp owns 16 q-rows. 64-key chunks.
// Pads: Qs/Ks/Ps 68 (row-gathers conflict-free), Vs 72 (col-gather c-free).
// ---------------------------------------------------------------------------
#define AQ    128
#define AK    64
#define QPW   68
#define VPW   72

#define AQS_OFF 0
#define AKS_OFF (AQ * QPW)                    //  8704
#define AVS_OFF (AKS_OFF + AK * QPW)          // 13056
#define APS_OFF (AVS_OFF + AK * VPW)          // 17664
#define ATTN_SMEM_WORDS (APS_OFF + AQ * QPW)  // 26368
#define ATTN_SMEM_BYTES (ATTN_SMEM_WORDS * 4) // 105,472 B

__global__ __launch_bounds__(256, 2)
void attn_mma_kernel(const uint32_t* __restrict__ Q, const uint32_t* __restrict__ K,
                     const uint32_t* __restrict__ V, uint32_t* __restrict__ AO)
{
    extern __shared__ uint32_t smw[];
    uint32_t* Qs = smw + AQS_OFF;
    uint32_t* Ks = smw + AKS_OFF;
    uint32_t* Vs = smw + AVS_OFF;
    uint32_t* Ps = smw + APS_OFF;

    const int tid  = threadIdx.x;
    const int wid  = tid >> 5;
    const int lane = tid & 31;
    const int gid  = lane >> 2;
    const int ctid = lane & 3;
    const int wrow = wid * 16;

    const int qt = blockIdx.x;
    const int h  = blockIdx.y;
    const int b  = blockIdx.z;
    const int q0 = qt * AQ;

    const uint32_t* Qb = Q + (((size_t)(b * NHEADS + h) * SEQ + q0) << 6);
    const uint32_t* Kb = K + (((size_t)(b * NHEADS + h) * SEQ) << 6);
    const uint32_t* Vb = V + (((size_t)(b * NHEADS + h) * SEQ) << 6);

    // ---- load Q tile (128x64, already tf32) ----
#pragma unroll
    for (int t = 0; t < 8; t++) {
        int idx = tid + t * 256;
        int row = idx >> 4;
        int c4  = (idx & 15) * 4;
        *(uint4*)&Qs[row * QPW + c4] = *(const uint4*)(Qb + row * HEADDIM + c4);
    }

    const float slope = exp2f(-(float)h / (float)NHEADS);
    const float scale = 0.125f;
    const float qg0 = (float)(q0 + wrow + gid);
    const float qg1 = qg0 + 8.0f;

    float oacc[8][4];
#pragma unroll
    for (int j = 0; j < 8; j++)
#pragma unroll
        for (int r = 0; r < 4; r++) oacc[j][r] = 0.0f;
    float m0 = -1e30f, m1 = -1e30f, l0 = 0.0f, l1 = 0.0f;

    for (int kt = 0; kt < SEQ; kt += AK) {
        __syncthreads();
        // ---- load K,V chunk (raw tf32) ----
#pragma unroll
        for (int t = 0; t < 4; t++) {
            int idx = tid + t * 256;
            int row = idx >> 4;
            int c4  = (idx & 15) * 4;
            *(uint4*)&Ks[row * QPW + c4] = *(const uint4*)(Kb + (size_t)(kt + row) * HEADDIM + c4);
            *(uint4*)&Vs[row * VPW + c4] = *(const uint4*)(Vb + (size_t)(kt + row) * HEADDIM + c4);
        }
        __syncthreads();

        // ---- S = Q K^T ----
        float sacc[8][4];
#pragma unroll
        for (int j = 0; j < 8; j++)
#pragma unroll
            for (int r = 0; r < 4; r++) sacc[j][r] = 0.0f;

#pragma unroll
        for (int ks = 0; ks < 8; ks++) {
            const int kb = ks * 8;
            uint32_t a[4];
            a[0] = Qs[(wrow + gid)     * QPW + kb + ctid];
            a[1] = Qs[(wrow + gid + 8) * QPW + kb + ctid];
            a[2] = Qs[(wrow + gid)     * QPW + kb + ctid + 4];
            a[3] = Qs[(wrow + gid + 8) * QPW + kb + ctid + 4];
#pragma unroll
            for (int nt = 0; nt < 8; nt++) {
                uint32_t bf[2];
                bf[0] = Ks[(nt * 8 + gid) * QPW + kb + ctid];
                bf[1] = Ks[(nt * 8 + gid) * QPW + kb + ctid + 4];
                mma_tf32_16x8x8(sacc[nt], a, bf);
            }
        }

        // ---- ALiBi + scale + row max ----
        float mx0 = -1e30f, mx1 = -1e30f;
#pragma unroll
        for (int nt = 0; nt < 8; nt++) {
            const float kg = (float)(kt + nt * 8 + 2 * ctid);
            sacc[nt][0] = sacc[nt][0] * scale + slope * (kg        - qg0);
            sacc[nt][1] = sacc[nt][1] * scale + slope * (kg + 1.0f - qg0);
            sacc[nt][2] = sacc[nt][2] * scale + slope * (kg        - qg1);
            sacc[nt][3] = sacc[nt][3] * scale + slope * (kg + 1.0f - qg1);
            mx0 = fmaxf(mx0, fmaxf(sacc[nt][0], sacc[nt][1]));
            mx1 = fmaxf(mx1, fmaxf(sacc[nt][2], sacc[nt][3]));
        }
#pragma unroll
        for (int msk = 1; msk < 4; msk <<= 1) {
            mx0 = fmaxf(mx0, __shfl_xor_sync(0xffffffffu, mx0, msk));
            mx1 = fmaxf(mx1, __shfl_xor_sync(0xffffffffu, mx1, msk));
        }

        const float m0n = fmaxf(m0, mx0);
        const float m1n = fmaxf(m1, mx1);
        const float corr0 = __expf(m0 - m0n);
        const float corr1 = __expf(m1 - m1n);
        m0 = m0n; m1 = m1n;

        // ---- P = exp(S - m) -> warp-private Ps rows (tf32) ----
        float ps0 = 0.0f, ps1 = 0.0f;
        const int r0 = wrow + gid, r1 = wrow + gid + 8;
#pragma unroll
        for (int nt = 0; nt < 8; nt++) {
            const int col = nt * 8 + 2 * ctid;
            float p0 = __expf(sacc[nt][0] - m0);
            float p1 = __expf(sacc[nt][1] - m0);
            float p2 = __expf(sacc[nt][2] - m1);
            float p3 = __expf(sacc[nt][3] - m1);
            ps0 += p0 + p1;
            ps1 += p2 + p3;
            *(uint2*)&Ps[r0 * QPW + col] = make_uint2(f32_to_tf32(p0), f32_to_tf32(p1));
            *(uint2*)&Ps[r1 * QPW + col] = make_uint2(f32_to_tf32(p2), f32_to_tf32(p3));
        }
#pragma unroll
        for (int msk = 1; msk < 4; msk <<= 1) {
            ps0 += __shfl_xor_sync(0xffffffffu, ps0, msk);
            ps1 += __shfl_xor_sync(0xffffffffu, ps1, msk);
        }
        l0 = l0 * corr0 + ps0;
        l1 = l1 * corr1 + ps1;

#pragma unroll
        for (int nt = 0; nt < 8; nt++) {
            oacc[nt][0] *= corr0; oacc[nt][1] *= corr0;
            oacc[nt][2] *= corr1; oacc[nt][3] *= corr1;
        }
        __syncwarp();

        // ---- O += P V ----
#pragma unroll
        for (int ks = 0; ks < 8; ks++) {
            const int kb = ks * 8;
            uint32_t a[4];
            a[0] = Ps[(wrow + gid)     * QPW + kb + ctid];
            a[1] = Ps[(wrow + gid + 8) * QPW + kb + ctid];
            a[2] = Ps[(wrow + gid)     * QPW + kb + ctid + 4];
            a[3] = Ps[(wrow + gid + 8) * QPW + kb + ctid + 4];
#pragma unroll
            for (int nt = 0; nt < 8; nt++) {
                uint32_t bf[2];
                bf[0] = Vs[(kb + ctid)     * VPW + nt * 8 + gid];
                bf[1] = Vs[(kb + ctid + 4) * VPW + nt * 8 + gid];
                mma_tf32_16x8x8(oacc[nt], a, bf);
            }
        }
    }

    // ---- normalize, convert to tf32, write AO ----
    const float inv0 = 1.0f / l0;
    const float inv1 = 1.0f / l1;
    const int qr0 = q0 + wrow + gid;
    const int qr1 = qr0 + 8;
    uint32_t* dst0 = AO + ((size_t)(b * SEQ + qr0) * DMODEL) + h * HEADDIM;
    uint32_t* dst1 = AO + ((size_t)(b * SEQ + qr1) * DMODEL) + h * HEADDIM;
#pragma unroll
    for (int nt = 0; nt < 8; nt++) {
        const int col = nt * 8 + 2 * ctid;
        *(uint2*)(dst0 + col) = make_uint2(f32_to_tf32(oacc[nt][0] * inv0),
                                           f32_to_tf32(oacc[nt][1] * inv0));
        *(uint2*)(dst1 + col) = make_uint2(f32_to_tf32(oacc[nt][2] * inv1),
                                           f32_to_tf32(oacc[nt][3] * inv1));
    }
}

// ---------------------------------------------------------------------------
// Launcher
// ---------------------------------------------------------------------------
extern "C" void kernel_launch(void* const* d_in, const int* in_sizes, int n_in,
                              void* d_out, int out_size)
{
    const float* x  = (const float*)d_in[0];
    const float* Wq = (const float*)d_in[1];
    const float* bq = (const float*)d_in[2];
    const float* Wk = (const float*)d_in[3];
    const float* bk = (const float*)d_in[4];
    const float* Wv = (const float*)d_in[5];
    const float* bv = (const float*)d_in[6];
    const float* Wo = (const float*)d_in[7];
    const float* bo = (const float*)d_in[8];
    float* out = (float*)d_out;

    uint32_t *gQ, *gK, *gV, *gAO, *gWt, *gXt;
    cudaGetSymbolAddress((void**)&gQ,  g_Q);
    cudaGetSymbolAddress((void**)&gK,  g_K);
    cudaGetSymbolAddress((void**)&gV,  g_V);
    cudaGetSymbolAddress((void**)&gAO, g_AO);
    cudaGetSymbolAddress((void**)&gWt, g_Wt);
    cudaGetSymbolAddress((void**)&gXt, g_Xt);

    cudaFuncSetAttribute(gemm_qkv_kernel, cudaFuncAttributeMaxDynamicSharedMemorySize,
                         GEMM_SMEM_BYTES);
    cudaFuncSetAttribute(gemm_out_kernel, cudaFuncAttributeMaxDynamicSharedMemorySize,
                         GEMM_SMEM_BYTES);
    cudaFuncSetAttribute(attn_mma_kernel, cudaFuncAttributeMaxDynamicSharedMemorySize,
                         ATTN_SMEM_BYTES);

    // Prep: weight transpose+convert, x convert
    transpose4_kernel<<<dim3(DMODEL / 32, DMODEL / 32, 4), dim3(32, 8)>>>(Wq, Wk, Wv, Wo);
    convert_x_kernel<<<(MTOT * DMODEL / 4) / 256, 256>>>(x);

    // QKV projections (one launch, grid.z selects head)
    dim3 qkvgrid(DMODEL / 128, MTOT / 128, 3);   // (8, 32, 3)
    gemm_qkv_kernel<<<qkvgrid, 256, GEMM_SMEM_BYTES>>>(gXt, gWt, bq, bk, bv, gQ, gK, gV);

    // Attention
    dim3 agrid(SEQ / AQ, NHEADS, BATCH);         // (16, 16, 2)
    attn_mma_kernel<<<agrid, 256, ATTN_SMEM_BYTES>>>(gQ, gK, gV, gAO);

    // Output projection
    dim3 ogrid(DMODEL / 128, MTOT / 128);        // (8, 32)
    gemm_out_kernel<<<ogrid, 256, GEMM_SMEM_BYTES>>>(gAO, gWt + 3 * (size_t)DMODEL * DMODEL,
                                                     bo, out);
}